// round 15
// baseline (speedup 1.0000x reference)
#include <cuda_runtime.h>
#include <cuda_fp16.h>
#include <cstdint>

#define N_NODES 131072
#define C_DIM   64
#define K_NEI   27
#define B_DIM   8
#define EMB_DIM 512
#define GN_EPS  1e-5f

// ---------------- scratch (device globals; no allocation allowed) -----------
__device__ __half g_h1[N_NODES * C_DIM];   // fp16 activations for MMA
__device__ float  g_h2[N_NODES * C_DIM];
__device__ uint2  g_w1f[K_NEI * 1024];     // W1 fp16 B-fragments
__device__ uint2  g_w2f[K_NEI * 1024];     // W2 fp16 B-fragments
__device__ float  g_sum[B_DIM * C_DIM];
__device__ float  g_ssq[B_DIM * C_DIM];
__device__ float  g_sum2[B_DIM * C_DIM];
__device__ float  g_ssq2[B_DIM * C_DIM];
__device__ float  g_cnt[B_DIM];
__device__ float  g_tvec[B_DIM * C_DIM];

// ---------------- helpers ----------------------------------------------------
__device__ __forceinline__ uint32_t smem_u32(const void* p) {
    uint32_t a;
    asm("{ .reg .u64 t; cvta.to.shared.u64 t, %1; cvt.u32.u64 %0, t; }" : "=r"(a) : "l"(p));
    return a;
}
__device__ __forceinline__ void cp16(uint32_t dst, const void* src) {
    asm volatile("cp.async.cg.shared.global [%0], [%1], 16;" :: "r"(dst), "l"(src) : "memory");
}
__device__ __forceinline__ void cp_commit() {
    asm volatile("cp.async.commit_group;" ::: "memory");
}
template <int N>
__device__ __forceinline__ void cp_wait() {
    asm volatile("cp.async.wait_group %0;" :: "n"(N) : "memory");
}
__device__ __forceinline__ void ldmatrix4(uint32_t* r, uint32_t addr) {
    asm volatile("ldmatrix.sync.aligned.m8n8.x4.shared.b16 {%0,%1,%2,%3}, [%4];"
                 : "=r"(r[0]), "=r"(r[1]), "=r"(r[2]), "=r"(r[3]) : "r"(addr));
}
__device__ __forceinline__ void mma_f16(float* d, const uint32_t* a, uint32_t b0, uint32_t b1) {
    asm volatile(
        "mma.sync.aligned.m16n8k16.row.col.f32.f16.f16.f32 "
        "{%0,%1,%2,%3}, {%4,%5,%6,%7}, {%8,%9}, {%0,%1,%2,%3};"
        : "+f"(d[0]), "+f"(d[1]), "+f"(d[2]), "+f"(d[3])
        : "r"(a[0]), "r"(a[1]), "r"(a[2]), "r"(a[3]), "r"(b0), "r"(b1));
}
__device__ __forceinline__ float silu_f(float v) { return v / (1.0f + __expf(-v)); }
__device__ __forceinline__ uint32_t pack_h2(float x, float y) {
    __half2 h = __floats2half2_rn(x, y);
    return *reinterpret_cast<uint32_t*>(&h);
}

// ---------------- GN stats (vectorized, block pre-reduction) -----------------
__global__ void stats_kernel(const float4* __restrict__ in4, const int* __restrict__ bid,
                             float* __restrict__ gsum, float* __restrict__ gssq,
                             float* __restrict__ gcnt, int do_cnt) {
    __shared__ float sred[2][2][64];   // [slot][sum/ssq][channel]
    __shared__ float scnt[2];
    __shared__ int sb0;
    const int t = threadIdx.x;
    const int c4 = t & 15;
    const int r  = t >> 4;
    const int base = blockIdx.x * 256;
    if (t == 0) sb0 = bid[base];
    reinterpret_cast<float*>(sred)[t] = 0.0f;
    if (t < 2) scnt[t] = 0.0f;
    __syncthreads();

    float4 s  = make_float4(0.f, 0.f, 0.f, 0.f);
    float4 ss = make_float4(0.f, 0.f, 0.f, 0.f);
    float cl = 0.0f;
    int cur = bid[base + r];

    #pragma unroll 4
    for (int i = 0; i < 16; i++) {
        int n = base + i * 16 + r;
        int b = bid[n];
        if (b != cur) {
            int slot = (cur != sb0) ? 1 : 0;
            atomicAdd(&sred[slot][0][c4 * 4 + 0], s.x);
            atomicAdd(&sred[slot][0][c4 * 4 + 1], s.y);
            atomicAdd(&sred[slot][0][c4 * 4 + 2], s.z);
            atomicAdd(&sred[slot][0][c4 * 4 + 3], s.w);
            atomicAdd(&sred[slot][1][c4 * 4 + 0], ss.x);
            atomicAdd(&sred[slot][1][c4 * 4 + 1], ss.y);
            atomicAdd(&sred[slot][1][c4 * 4 + 2], ss.z);
            atomicAdd(&sred[slot][1][c4 * 4 + 3], ss.w);
            if (c4 == 0) atomicAdd(&scnt[slot], cl);
            s = make_float4(0.f, 0.f, 0.f, 0.f);
            ss = make_float4(0.f, 0.f, 0.f, 0.f);
            cl = 0.0f; cur = b;
        }
        float4 v = in4[(size_t)n * 16 + c4];
        s.x += v.x; s.y += v.y; s.z += v.z; s.w += v.w;
        ss.x += v.x * v.x; ss.y += v.y * v.y;
        ss.z += v.z * v.z; ss.w += v.w * v.w;
        cl += 1.0f;
    }
    {
        int slot = (cur != sb0) ? 1 : 0;
        atomicAdd(&sred[slot][0][c4 * 4 + 0], s.x);
        atomicAdd(&sred[slot][0][c4 * 4 + 1], s.y);
        atomicAdd(&sred[slot][0][c4 * 4 + 2], s.z);
        atomicAdd(&sred[slot][0][c4 * 4 + 3], s.w);
        atomicAdd(&sred[slot][1][c4 * 4 + 0], ss.x);
        atomicAdd(&sred[slot][1][c4 * 4 + 1], ss.y);
        atomicAdd(&sred[slot][1][c4 * 4 + 2], ss.z);
        atomicAdd(&sred[slot][1][c4 * 4 + 3], ss.w);
        if (c4 == 0) atomicAdd(&scnt[slot], cl);
    }
    __syncthreads();

    int slot = t >> 7, which = (t >> 6) & 1, c = t & 63;
    int b = sb0 + slot;
    if (b < B_DIM) {
        float v = sred[slot][which][c];
        atomicAdd(which ? &gssq[b * 64 + c] : &gsum[b * 64 + c], v);
    }
    if (do_cnt && t < 2 && sb0 + t < B_DIM) atomicAdd(&gcnt[sb0 + t], scnt[t]);
}

// ---------------- normalize + SiLU -> fp16; finalize fused per block ---------
__global__ void normact_kernel(const float4* __restrict__ in, const int* __restrict__ bid,
                               const float* __restrict__ gsum, const float* __restrict__ gssq,
                               const float* __restrict__ gcnt,
                               const float* __restrict__ gamma, const float* __restrict__ beta,
                               uint4* __restrict__ out) {
    __shared__ float ssc[2][64], ssh[2][64];
    __shared__ int sb2[2];
    int t = threadIdx.x;
    int nbase = blockIdx.x * 32;
    if (t == 0) { sb2[0] = bid[nbase]; sb2[1] = bid[nbase + 31]; }
    __syncthreads();
    if (t < 128) {
        int which = t >> 6, c = t & 63, b = sb2[which];
        int g0 = c & ~1;
        float denom = gcnt[b] * 2.0f;
        float m = (gsum[b * 64 + g0] + gsum[b * 64 + g0 + 1]) / denom;
        float v = (gssq[b * 64 + g0] + gssq[b * 64 + g0 + 1]) / denom - m * m;
        float rs = rsqrtf(v + GN_EPS);
        float sc = gamma[c] * rs;
        ssc[which][c] = sc;
        ssh[which][c] = beta[c] - m * sc;
    }
    __syncthreads();
    int idx = blockIdx.x * 256 + t;
    int n = idx >> 3, q = idx & 7;
    int slot = (bid[n] != sb2[0]) ? 1 : 0;
    float4 v0 = in[n * 16 + q * 2];
    float4 v1 = in[n * 16 + q * 2 + 1];
    const float4* sc4 = reinterpret_cast<const float4*>(ssc[slot]);
    const float4* sh4 = reinterpret_cast<const float4*>(ssh[slot]);
    float4 sc0 = sc4[q * 2], sc1 = sc4[q * 2 + 1];
    float4 sh0 = sh4[q * 2], sh1 = sh4[q * 2 + 1];
    float r0 = silu_f(v0.x * sc0.x + sh0.x);
    float r1 = silu_f(v0.y * sc0.y + sh0.y);
    float r2 = silu_f(v0.z * sc0.z + sh0.z);
    float r3 = silu_f(v0.w * sc0.w + sh0.w);
    float r4 = silu_f(v1.x * sc1.x + sh1.x);
    float r5 = silu_f(v1.y * sc1.y + sh1.y);
    float r6 = silu_f(v1.z * sc1.z + sh1.z);
    float r7 = silu_f(v1.w * sc1.w + sh1.w);
    out[idx] = make_uint4(pack_h2(r0, r1), pack_h2(r2, r3),
                          pack_h2(r4, r5), pack_h2(r6, r7));
}

__global__ void time_kernel(const float* __restrict__ emb, const float* __restrict__ Wt,
                            const float* __restrict__ bt, float* __restrict__ tout) {
    __shared__ float se[B_DIM * EMB_DIM];
    int t = threadIdx.x;
    for (int i = t; i < B_DIM * EMB_DIM; i += 512) se[i] = silu_f(emb[i]);
    __syncthreads();
    int b = t >> 6, co = t & 63;
    float acc = bt[co];
    const float* e = se + b * EMB_DIM;
    #pragma unroll 8
    for (int k = 0; k < EMB_DIM; k++) acc += e[k] * Wt[k * 64 + co];
    tout[t] = acc;
}

// ---------------- prep: weights -> fp16 B-fragments + zero all stat bufs -----
__device__ __forceinline__ void prep_w_one(const float* W, uint2* Wf, int i) {
    int k = i >> 10;
    int r = i & 1023;
    int grp = r >> 5, lane = r & 31;
    int ks = grp >> 3, c = grp & 7;
    int gid = lane >> 2, tig = lane & 3;
    int ci0 = ks * 16 + 2 * tig;
    int co = c * 8 + gid;
    const float* wk = W + (size_t)k * 4096;
    uint2 v;
    v.x = pack_h2(wk[ci0 * 64 + co],       wk[(ci0 + 1) * 64 + co]);
    v.y = pack_h2(wk[(ci0 + 8) * 64 + co], wk[(ci0 + 9) * 64 + co]);
    Wf[i] = v;
}

__global__ void prep_kernel(const float* __restrict__ W1, const float* __restrict__ W2,
                            uint2* __restrict__ w1f, uint2* __restrict__ w2f,
                            float* gsum, float* gssq, float* gsum2, float* gssq2,
                            float* gcnt) {
    int b = blockIdx.x, t = threadIdx.x;
    if (b < 108) {
        int i = b * 256 + t;
        if (i < K_NEI * 1024) prep_w_one(W1, w1f, i);
    } else if (b < 216) {
        int i = (b - 108) * 256 + t;
        if (i < K_NEI * 1024) prep_w_one(W2, w2f, i);
    } else {
        for (int i = t; i < B_DIM * C_DIM; i += 256) {
            gsum[i] = 0.0f; gssq[i] = 0.0f;
            gsum2[i] = 0.0f; gssq2[i] = 0.0f;
        }
        if (t < B_DIM) gcnt[t] = 0.0f;
    }
}

// ---------------- fp16 mma.sync gather-conv, 3-stage per-warp pipeline -------
// Mainloop byte-identical to R14 (proven). Epilogue optionally accumulates
// GN2 per-(batch,channel) sum/ssq (conv1 only) via smem reduction in the
// now-dead stage-0 A-buffer.
#define TN        256
#define SM_TOTAL  (3 * 32768)                 // half xs[3][256*64] : 96KB

__global__ void __launch_bounds__(256, 2) conv_mma_kernel(
    const __half* __restrict__ h, const int* __restrict__ neigh,
    const uint2* __restrict__ wf, const float* __restrict__ bias,
    const float* __restrict__ tvec, const int* __restrict__ bid,
    const float* __restrict__ resid,
    float* __restrict__ gsum2, float* __restrict__ gssq2,
    float* __restrict__ out)
{
    extern __shared__ char smem[];
    const uint32_t xs_sm = smem_u32(smem);
    float* sred = reinterpret_cast<float*>(smem);   // reused post-loop: 2*2*64 floats

    const int t = threadIdx.x;
    const int w = t >> 5, l = t & 31;
    const int base = blockIdx.x * TN;

    float acc[2][8][4];
    #pragma unroll
    for (int ti = 0; ti < 2; ti++)
        #pragma unroll
        for (int c = 0; c < 8; c++)
            #pragma unroll
            for (int j = 0; j < 4; j++) acc[ti][c][j] = 0.0f;

    // ldmatrix addresses (per lane), stage 0; stage s adds s*32768
    uint32_t amat[2][4];
    {
        int row_local = l & 15;
        int hi = l >> 4;
        #pragma unroll
        for (int ti = 0; ti < 2; ti++) {
            int row = w * 32 + ti * 16 + row_local;
            #pragma unroll
            for (int ks = 0; ks < 4; ks++) {
                int chunk = 2 * ks + hi;
                amat[ti][ks] = xs_sm + row * 128 + (((chunk ^ (l & 7))) << 4);
            }
        }
    }

    const int grow4 = l >> 3;      // 0..3: row within 4-row warp-op
    const int chunk = l & 7;       // 16B chunk within the 128B row

    // ---- stage k into buffer k%3: warp stages its OWN rows only ------------
    auto issue = [&](int k, int st) {
        const uint32_t soff = (uint32_t)st * 32768u;
        #pragma unroll
        for (int i = 0; i < 8; i++) {
            int row = w * 32 + i * 4 + grow4;
            int nbv = neigh[(size_t)(base + row) * K_NEI + k];   // lane-broadcast
            const char* src = reinterpret_cast<const char*>(h + (size_t)nbv * 64)
                              + chunk * 16;
            uint32_t dst = xs_sm + soff + row * 128 + ((chunk ^ (row & 7)) << 4);
            cp16(dst, src);
        }
        cp_commit();
    };

    issue(0, 0);
    issue(1, 1);

    int st = 0;                    // k % 3
    for (int k = 0; k < K_NEI; k++) {
        if (k + 1 < K_NEI) cp_wait<1>(); else cp_wait<0>();
        __syncwarp();              // all lanes' groups done -> warp's rows ready

        // issue k+2 FIRST (buffer (k+2)%3 was consumed at iteration k-1)
        int st2 = st + 2 - ((st >= 1) ? 3 : 0);   // (st+2)%3
        if (k + 2 < K_NEI) issue(k + 2, st2);

        const uint32_t bufoff = (uint32_t)st * 32768u;
        const uint2* wk = wf + (size_t)k * 1024;

        #pragma unroll
        for (int ks = 0; ks < 4; ks++) {
            uint32_t a0[4], a1[4];
            ldmatrix4(a0, amat[0][ks] + bufoff);
            ldmatrix4(a1, amat[1][ks] + bufoff);
            #pragma unroll
            for (int c = 0; c < 8; c++) {
                uint2 b = wk[(ks * 8 + c) * 32 + l];   // L1-resident LDG.64
                mma_f16(acc[0][c], a0, b.x, b.y);
                mma_f16(acc[1][c], a1, b.x, b.y);
            }
        }
        st = (st == 2) ? 0 : st + 1;
    }

    // ---- epilogue: bias (+tvec) (+resid), direct STG; optional GN2 stats ----
    const int g = l >> 2, tig = l & 3;
    const bool do_stats = (gsum2 != nullptr);

    if (do_stats) {                 // smem stages all consumed; reuse for sred
        __syncthreads();
        if (t < 256) sred[t] = 0.0f;   // sred[slot][which][ch] = 2*2*64
        __syncthreads();
    }

    const int b0 = bid[base];
    const int rbase = base + w * 32 + g;
    int slots[2][2] = {{0, 0}, {0, 0}};
    bool uni = true;
    if (tvec || do_stats) {
        #pragma unroll
        for (int ti = 0; ti < 2; ti++) {
            int r0 = rbase + ti * 16;
            slots[ti][0] = (bid[r0] != b0) ? 1 : 0;
            slots[ti][1] = (bid[r0 + 8] != b0) ? 1 : 0;
        }
        uni = (slots[0][0] == slots[1][1]);   // sorted bids -> monotone slots
    }

    float ssum[8][2] = {}, sssq[8][2] = {};

    #pragma unroll
    for (int ti = 0; ti < 2; ti++) {
        const int r0 = rbase + ti * 16;
        const int r1 = r0 + 8;
        const float* tvp0 = nullptr; const float* tvp1 = nullptr;
        if (tvec) {
            tvp0 = tvec + (size_t)(b0 + slots[ti][0]) * 64;
            tvp1 = tvec + (size_t)(b0 + slots[ti][1]) * 64;
        }
        #pragma unroll
        for (int c = 0; c < 8; c++) {
            int co = c * 8 + 2 * tig;
            float2 bb = *reinterpret_cast<const float2*>(bias + co);
            float2 o0 = make_float2(acc[ti][c][0] + bb.x, acc[ti][c][1] + bb.y);
            float2 o1 = make_float2(acc[ti][c][2] + bb.x, acc[ti][c][3] + bb.y);
            if (tvec) {
                float2 tv0 = *reinterpret_cast<const float2*>(tvp0 + co);
                float2 tv1 = *reinterpret_cast<const float2*>(tvp1 + co);
                o0.x += tv0.x; o0.y += tv0.y;
                o1.x += tv1.x; o1.y += tv1.y;
            }
            if (resid) {
                float2 q0 = *reinterpret_cast<const float2*>(resid + (size_t)r0 * 64 + co);
                float2 q1 = *reinterpret_cast<const float2*>(resid + (size_t)r1 * 64 + co);
                o0.x += q0.x; o0.y += q0.y;
                o1.x += q1.x; o1.y += q1.y;
            }
            *reinterpret_cast<float2*>(out + (size_t)r0 * 64 + co) = o0;
            *reinterpret_cast<float2*>(out + (size_t)r1 * 64 + co) = o1;
            if (do_stats) {
                if (uni) {
                    ssum[c][0] += o0.x + o1.x;
                    ssum[c][1] += o0.y + o1.y;
                    sssq[c][0] += o0.x * o0.x + o1.x * o1.x;
                    sssq[c][1] += o0.y * o0.y + o1.y * o1.y;
                } else {
                    int s0 = slots[ti][0] * 128, s1 = slots[ti][1] * 128;
                    atomicAdd(&sred[s0 + co], o0.x);
                    atomicAdd(&sred[s0 + co + 1], o0.y);
                    atomicAdd(&sred[s0 + 64 + co], o0.x * o0.x);
                    atomicAdd(&sred[s0 + 64 + co + 1], o0.y * o0.y);
                    atomicAdd(&sred[s1 + co], o1.x);
                    atomicAdd(&sred[s1 + co + 1], o1.y);
                    atomicAdd(&sred[s1 + 64 + co], o1.x * o1.x);
                    atomicAdd(&sred[s1 + 64 + co + 1], o1.y * o1.y);
                }
            }
        }
    }

    if (do_stats) {
        if (uni) {
            int s = slots[0][0] * 128;
            #pragma unroll
            for (int c = 0; c < 8; c++) {
                int co = c * 8 + 2 * tig;
                atomicAdd(&sred[s + co], ssum[c][0]);
                atomicAdd(&sred[s + co + 1], ssum[c][1]);
                atomicAdd(&sred[s + 64 + co], sssq[c][0]);
                atomicAdd(&sred[s + 64 + co + 1], sssq[c][1]);
            }
        }
        __syncthreads();
        // flush: t -> (slot, which, co)
        int slot = t >> 7, which = (t >> 6) & 1, co = t & 63;
        int b = b0 + slot;
        if (b < B_DIM) {
            float v = sred[slot * 128 + which * 64 + co];
            atomicAdd(which ? &gssq2[b * 64 + co] : &gsum2[b * 64 + co], v);
        }
    }
}

// ---------------- launch ------------------------------------------------------
extern "C" void kernel_launch(void* const* d_in, const int* in_sizes, int n_in,
                              void* d_out, int out_size) {
    const float* x    = (const float*)d_in[0];
    const float* temb = (const float*)d_in[1];
    const int*   bid  = (const int*)  d_in[2];
    const int*   nei  = (const int*)  d_in[3];
    const float* ga1  = (const float*)d_in[4];
    const float* be1  = (const float*)d_in[5];
    const float* W1   = (const float*)d_in[6];
    const float* b1   = (const float*)d_in[7];
    const float* Wt   = (const float*)d_in[8];
    const float* bt   = (const float*)d_in[9];
    const float* ga2  = (const float*)d_in[10];
    const float* be2  = (const float*)d_in[11];
    const float* W2   = (const float*)d_in[12];
    const float* b2   = (const float*)d_in[13];
    float* out = (float*)d_out;

    __half* h1;
    float *h2, *sum, *ssq, *sum2, *ssq2, *cnt, *tvec;
    uint2 *w1f, *w2f;
    cudaGetSymbolAddress((void**)&h1,   g_h1);
    cudaGetSymbolAddress((void**)&h2,   g_h2);
    cudaGetSymbolAddress((void**)&w1f,  g_w1f);
    cudaGetSymbolAddress((void**)&w2f,  g_w2f);
    cudaGetSymbolAddress((void**)&sum,  g_sum);
    cudaGetSymbolAddress((void**)&ssq,  g_ssq);
    cudaGetSymbolAddress((void**)&sum2, g_sum2);
    cudaGetSymbolAddress((void**)&ssq2, g_ssq2);
    cudaGetSymbolAddress((void**)&cnt,  g_cnt);
    cudaGetSymbolAddress((void**)&tvec, g_tvec);

    cudaFuncSetAttribute(conv_mma_kernel,
                         cudaFuncAttributeMaxDynamicSharedMemorySize, SM_TOTAL);

    const int statsBlocks = N_NODES / 256;       // 512
    const int naBlocks    = (N_NODES * 8) / 256; // 4096
    const int convBlocks  = N_NODES / TN;        // 512

    // prep (weights + zero stats) and time embedding
    prep_kernel<<<217, 256>>>(W1, W2, w1f, w2f, sum, ssq, sum2, ssq2, cnt);
    time_kernel<<<1, 512>>>(temb, Wt, bt, tvec);

    // GN1 stats -> normact1 (finalize fused) -> h1 fp16
    stats_kernel<<<statsBlocks, 256>>>((const float4*)x, bid, sum, ssq, cnt, 1);
    normact_kernel<<<naBlocks, 256>>>((const float4*)x, bid, sum, ssq, cnt,
                                      ga1, be1, (uint4*)h1);

    // conv1 (3-stage per-warp) + t[batch] -> h2, GN2 stats fused in epilogue
    conv_mma_kernel<<<convBlocks, 256, SM_TOTAL>>>(h1, nei, w1f, b1, tvec, bid,
                                                   nullptr, sum2, ssq2, h2);

    // normact2 (finalize fused, counts reused from GN1) -> h1 fp16
    normact_kernel<<<naBlocks, 256>>>((const float4*)h2, bid, sum2, ssq2, cnt,
                                      ga2, be2, (uint4*)h1);

    // conv2 (3-stage per-warp) + residual -> out
    conv_mma_kernel<<<convBlocks, 256, SM_TOTAL>>>(h1, nei, w2f, b2, nullptr, bid,
                                                   x, nullptr, nullptr, out);
}

// round 16
// speedup vs baseline: 1.2432x; 1.2432x over previous
#include <cuda_runtime.h>
#include <cuda_fp16.h>
#include <cstdint>

#define N_NODES 131072
#define C_DIM   64
#define K_NEI   27
#define B_DIM   8
#define EMB_DIM 512
#define GN_EPS  1e-5f

// ---------------- scratch (device globals; no allocation allowed) -----------
__device__ __half g_h1[N_NODES * C_DIM];   // fp16 activations for MMA
__device__ float  g_h2[N_NODES * C_DIM];
__device__ uint2  g_w1f[K_NEI * 1024];     // W1 fp16 B-fragments
__device__ uint2  g_w2f[K_NEI * 1024];     // W2 fp16 B-fragments
__device__ float  g_sum[B_DIM * C_DIM];
__device__ float  g_ssq[B_DIM * C_DIM];
__device__ float  g_sum2[B_DIM * C_DIM];
__device__ float  g_ssq2[B_DIM * C_DIM];
__device__ float  g_cnt[B_DIM];
__device__ float  g_tvec[B_DIM * C_DIM];

// ---------------- helpers ----------------------------------------------------
__device__ __forceinline__ uint32_t smem_u32(const void* p) {
    uint32_t a;
    asm("{ .reg .u64 t; cvta.to.shared.u64 t, %1; cvt.u32.u64 %0, t; }" : "=r"(a) : "l"(p));
    return a;
}
__device__ __forceinline__ void cp16(uint32_t dst, const void* src) {
    asm volatile("cp.async.cg.shared.global [%0], [%1], 16;" :: "r"(dst), "l"(src) : "memory");
}
__device__ __forceinline__ void cp_commit() {
    asm volatile("cp.async.commit_group;" ::: "memory");
}
template <int N>
__device__ __forceinline__ void cp_wait() {
    asm volatile("cp.async.wait_group %0;" :: "n"(N) : "memory");
}
__device__ __forceinline__ void ldmatrix4(uint32_t* r, uint32_t addr) {
    asm volatile("ldmatrix.sync.aligned.m8n8.x4.shared.b16 {%0,%1,%2,%3}, [%4];"
                 : "=r"(r[0]), "=r"(r[1]), "=r"(r[2]), "=r"(r[3]) : "r"(addr));
}
__device__ __forceinline__ void mma_f16(float* d, const uint32_t* a, uint32_t b0, uint32_t b1) {
    asm volatile(
        "mma.sync.aligned.m16n8k16.row.col.f32.f16.f16.f32 "
        "{%0,%1,%2,%3}, {%4,%5,%6,%7}, {%8,%9}, {%0,%1,%2,%3};"
        : "+f"(d[0]), "+f"(d[1]), "+f"(d[2]), "+f"(d[3])
        : "r"(a[0]), "r"(a[1]), "r"(a[2]), "r"(a[3]), "r"(b0), "r"(b1));
}
__device__ __forceinline__ float silu_f(float v) { return v / (1.0f + __expf(-v)); }
__device__ __forceinline__ uint32_t pack_h2(float x, float y) {
    __half2 h = __floats2half2_rn(x, y);
    return *reinterpret_cast<uint32_t*>(&h);
}

// ---------------- GN stats (vectorized, block pre-reduction) -----------------
__global__ void stats_kernel(const float4* __restrict__ in4, const int* __restrict__ bid,
                             float* __restrict__ gsum, float* __restrict__ gssq,
                             float* __restrict__ gcnt, int do_cnt) {
    __shared__ float sred[2][2][64];   // [slot][sum/ssq][channel]
    __shared__ float scnt[2];
    __shared__ int sb0;
    const int t = threadIdx.x;
    const int c4 = t & 15;
    const int r  = t >> 4;
    const int base = blockIdx.x * 256;
    if (t == 0) sb0 = bid[base];
    reinterpret_cast<float*>(sred)[t] = 0.0f;
    if (t < 2) scnt[t] = 0.0f;
    __syncthreads();

    float4 s  = make_float4(0.f, 0.f, 0.f, 0.f);
    float4 ss = make_float4(0.f, 0.f, 0.f, 0.f);
    float cl = 0.0f;
    int cur = bid[base + r];

    #pragma unroll 4
    for (int i = 0; i < 16; i++) {
        int n = base + i * 16 + r;
        int b = bid[n];
        if (b != cur) {
            int slot = (cur != sb0) ? 1 : 0;
            atomicAdd(&sred[slot][0][c4 * 4 + 0], s.x);
            atomicAdd(&sred[slot][0][c4 * 4 + 1], s.y);
            atomicAdd(&sred[slot][0][c4 * 4 + 2], s.z);
            atomicAdd(&sred[slot][0][c4 * 4 + 3], s.w);
            atomicAdd(&sred[slot][1][c4 * 4 + 0], ss.x);
            atomicAdd(&sred[slot][1][c4 * 4 + 1], ss.y);
            atomicAdd(&sred[slot][1][c4 * 4 + 2], ss.z);
            atomicAdd(&sred[slot][1][c4 * 4 + 3], ss.w);
            if (c4 == 0) atomicAdd(&scnt[slot], cl);
            s = make_float4(0.f, 0.f, 0.f, 0.f);
            ss = make_float4(0.f, 0.f, 0.f, 0.f);
            cl = 0.0f; cur = b;
        }
        float4 v = in4[(size_t)n * 16 + c4];
        s.x += v.x; s.y += v.y; s.z += v.z; s.w += v.w;
        ss.x += v.x * v.x; ss.y += v.y * v.y;
        ss.z += v.z * v.z; ss.w += v.w * v.w;
        cl += 1.0f;
    }
    {
        int slot = (cur != sb0) ? 1 : 0;
        atomicAdd(&sred[slot][0][c4 * 4 + 0], s.x);
        atomicAdd(&sred[slot][0][c4 * 4 + 1], s.y);
        atomicAdd(&sred[slot][0][c4 * 4 + 2], s.z);
        atomicAdd(&sred[slot][0][c4 * 4 + 3], s.w);
        atomicAdd(&sred[slot][1][c4 * 4 + 0], ss.x);
        atomicAdd(&sred[slot][1][c4 * 4 + 1], ss.y);
        atomicAdd(&sred[slot][1][c4 * 4 + 2], ss.z);
        atomicAdd(&sred[slot][1][c4 * 4 + 3], ss.w);
        if (c4 == 0) atomicAdd(&scnt[slot], cl);
    }
    __syncthreads();

    int slot = t >> 7, which = (t >> 6) & 1, c = t & 63;
    int b = sb0 + slot;
    if (b < B_DIM) {
        float v = sred[slot][which][c];
        atomicAdd(which ? &gssq[b * 64 + c] : &gsum[b * 64 + c], v);
    }
    if (do_cnt && t < 2 && sb0 + t < B_DIM) atomicAdd(&gcnt[sb0 + t], scnt[t]);
}

// ---------------- normalize + SiLU -> fp16; finalize fused per block ---------
__global__ void normact_kernel(const float4* __restrict__ in, const int* __restrict__ bid,
                               const float* __restrict__ gsum, const float* __restrict__ gssq,
                               const float* __restrict__ gcnt,
                               const float* __restrict__ gamma, const float* __restrict__ beta,
                               uint4* __restrict__ out) {
    __shared__ float ssc[2][64], ssh[2][64];
    __shared__ int sb2[2];
    int t = threadIdx.x;
    int nbase = blockIdx.x * 32;
    if (t == 0) { sb2[0] = bid[nbase]; sb2[1] = bid[nbase + 31]; }
    __syncthreads();
    if (t < 128) {
        int which = t >> 6, c = t & 63, b = sb2[which];
        int g0 = c & ~1;
        float denom = gcnt[b] * 2.0f;
        float m = (gsum[b * 64 + g0] + gsum[b * 64 + g0 + 1]) / denom;
        float v = (gssq[b * 64 + g0] + gssq[b * 64 + g0 + 1]) / denom - m * m;
        float rs = rsqrtf(v + GN_EPS);
        float sc = gamma[c] * rs;
        ssc[which][c] = sc;
        ssh[which][c] = beta[c] - m * sc;
    }
    __syncthreads();
    int idx = blockIdx.x * 256 + t;
    int n = idx >> 3, q = idx & 7;
    int slot = (bid[n] != sb2[0]) ? 1 : 0;
    float4 v0 = in[n * 16 + q * 2];
    float4 v1 = in[n * 16 + q * 2 + 1];
    const float4* sc4 = reinterpret_cast<const float4*>(ssc[slot]);
    const float4* sh4 = reinterpret_cast<const float4*>(ssh[slot]);
    float4 sc0 = sc4[q * 2], sc1 = sc4[q * 2 + 1];
    float4 sh0 = sh4[q * 2], sh1 = sh4[q * 2 + 1];
    float r0 = silu_f(v0.x * sc0.x + sh0.x);
    float r1 = silu_f(v0.y * sc0.y + sh0.y);
    float r2 = silu_f(v0.z * sc0.z + sh0.z);
    float r3 = silu_f(v0.w * sc0.w + sh0.w);
    float r4 = silu_f(v1.x * sc1.x + sh1.x);
    float r5 = silu_f(v1.y * sc1.y + sh1.y);
    float r6 = silu_f(v1.z * sc1.z + sh1.z);
    float r7 = silu_f(v1.w * sc1.w + sh1.w);
    out[idx] = make_uint4(pack_h2(r0, r1), pack_h2(r2, r3),
                          pack_h2(r4, r5), pack_h2(r6, r7));
}

// ---------------- time embedding: 8 blocks (one per batch), 64 threads -------
__global__ void time_kernel(const float* __restrict__ emb, const float* __restrict__ Wt,
                            const float* __restrict__ bt, float* __restrict__ tout) {
    __shared__ float se[EMB_DIM];
    int b = blockIdx.x;
    int co = threadIdx.x;            // 64 threads
    for (int i = co; i < EMB_DIM; i += 64) se[i] = silu_f(emb[b * EMB_DIM + i]);
    __syncthreads();
    float acc = bt[co];
    #pragma unroll 8
    for (int k = 0; k < EMB_DIM; k++) acc += se[k] * Wt[k * 64 + co];
    tout[b * 64 + co] = acc;
}

// ---------------- prep: weights -> fp16 B-fragments + zero all stat bufs -----
__device__ __forceinline__ void prep_w_one(const float* W, uint2* Wf, int i) {
    int k = i >> 10;
    int r = i & 1023;
    int grp = r >> 5, lane = r & 31;
    int ks = grp >> 3, c = grp & 7;
    int gid = lane >> 2, tig = lane & 3;
    int ci0 = ks * 16 + 2 * tig;
    int co = c * 8 + gid;
    const float* wk = W + (size_t)k * 4096;
    uint2 v;
    v.x = pack_h2(wk[ci0 * 64 + co],       wk[(ci0 + 1) * 64 + co]);
    v.y = pack_h2(wk[(ci0 + 8) * 64 + co], wk[(ci0 + 9) * 64 + co]);
    Wf[i] = v;
}

__global__ void prep_kernel(const float* __restrict__ W1, const float* __restrict__ W2,
                            uint2* __restrict__ w1f, uint2* __restrict__ w2f,
                            float* gsum, float* gssq, float* gsum2, float* gssq2,
                            float* gcnt) {
    int b = blockIdx.x, t = threadIdx.x;
    if (b < 108) {
        int i = b * 256 + t;
        if (i < K_NEI * 1024) prep_w_one(W1, w1f, i);
    } else if (b < 216) {
        int i = (b - 108) * 256 + t;
        if (i < K_NEI * 1024) prep_w_one(W2, w2f, i);
    } else {
        for (int i = t; i < B_DIM * C_DIM; i += 256) {
            gsum[i] = 0.0f; gssq[i] = 0.0f;
            gsum2[i] = 0.0f; gssq2[i] = 0.0f;
        }
        if (t < B_DIM) gcnt[t] = 0.0f;
    }
}

// ---------------- fp16 mma.sync gather-conv, 3-stage per-warp pipeline -------
// R14 byte-identical (proven best). 256 nodes/block, 256 threads (8 warps x
// 32 rows), 2 CTAs/SM. A stages warp-private -> no block barriers; 3 stages +
// issue-before-compute gives 2-iteration gather lead. Weights direct LDG
// (L1-resident); neighbor ids direct LDG (lane-broadcast, L2-resident).
#define TN        256
#define SM_TOTAL  (3 * 32768)                 // half xs[3][256*64] : 96KB

__global__ void __launch_bounds__(256, 2) conv_mma_kernel(
    const __half* __restrict__ h, const int* __restrict__ neigh,
    const uint2* __restrict__ wf, const float* __restrict__ bias,
    const float* __restrict__ tvec, const int* __restrict__ bid,
    const float* __restrict__ resid, float* __restrict__ out)
{
    extern __shared__ char smem[];
    const uint32_t xs_sm = smem_u32(smem);

    const int t = threadIdx.x;
    const int w = t >> 5, l = t & 31;
    const int base = blockIdx.x * TN;

    float acc[2][8][4];
    #pragma unroll
    for (int ti = 0; ti < 2; ti++)
        #pragma unroll
        for (int c = 0; c < 8; c++)
            #pragma unroll
            for (int j = 0; j < 4; j++) acc[ti][c][j] = 0.0f;

    // ldmatrix addresses (per lane), stage 0; stage s adds s*32768
    uint32_t amat[2][4];
    {
        int row_local = l & 15;
        int hi = l >> 4;
        #pragma unroll
        for (int ti = 0; ti < 2; ti++) {
            int row = w * 32 + ti * 16 + row_local;
            #pragma unroll
            for (int ks = 0; ks < 4; ks++) {
                int chunk = 2 * ks + hi;
                amat[ti][ks] = xs_sm + row * 128 + (((chunk ^ (l & 7))) << 4);
            }
        }
    }

    const int grow4 = l >> 3;      // 0..3: row within 4-row warp-op
    const int chunk = l & 7;       // 16B chunk within the 128B row

    // ---- stage k into buffer k%3: warp stages its OWN rows only ------------
    auto issue = [&](int k, int st) {
        const uint32_t soff = (uint32_t)st * 32768u;
        #pragma unroll
        for (int i = 0; i < 8; i++) {
            int row = w * 32 + i * 4 + grow4;
            int nbv = neigh[(size_t)(base + row) * K_NEI + k];   // lane-broadcast
            const char* src = reinterpret_cast<const char*>(h + (size_t)nbv * 64)
                              + chunk * 16;
            uint32_t dst = xs_sm + soff + row * 128 + ((chunk ^ (row & 7)) << 4);
            cp16(dst, src);
        }
        cp_commit();
    };

    issue(0, 0);
    issue(1, 1);

    int st = 0;                    // k % 3
    for (int k = 0; k < K_NEI; k++) {
        if (k + 1 < K_NEI) cp_wait<1>(); else cp_wait<0>();
        __syncwarp();              // all lanes' groups done -> warp's rows ready

        // issue k+2 FIRST (buffer (k+2)%3 was consumed at iteration k-1)
        int st2 = st + 2 - ((st >= 1) ? 3 : 0);   // (st+2)%3
        if (k + 2 < K_NEI) issue(k + 2, st2);

        const uint32_t bufoff = (uint32_t)st * 32768u;
        const uint2* wk = wf + (size_t)k * 1024;

        #pragma unroll
        for (int ks = 0; ks < 4; ks++) {
            uint32_t a0[4], a1[4];
            ldmatrix4(a0, amat[0][ks] + bufoff);
            ldmatrix4(a1, amat[1][ks] + bufoff);
            #pragma unroll
            for (int c = 0; c < 8; c++) {
                uint2 b = wk[(ks * 8 + c) * 32 + l];   // L1-resident LDG.64
                mma_f16(acc[0][c], a0, b.x, b.y);
                mma_f16(acc[1][c], a1, b.x, b.y);
            }
        }
        st = (st == 2) ? 0 : st + 1;
    }

    // ---- epilogue: bias (+tvec) (+resid), direct STG ------------------------
    const int g = l >> 2, tig = l & 3;
    #pragma unroll
    for (int ti = 0; ti < 2; ti++) {
        const int r0 = base + w * 32 + ti * 16 + g;
        const int r1 = r0 + 8;
        const float* tvp0 = nullptr; const float* tvp1 = nullptr;
        if (tvec) {
            tvp0 = tvec + (size_t)bid[r0] * 64;
            tvp1 = tvec + (size_t)bid[r1] * 64;
        }
        #pragma unroll
        for (int c = 0; c < 8; c++) {
            int co = c * 8 + 2 * tig;
            float2 bb = *reinterpret_cast<const float2*>(bias + co);
            float2 o0 = make_float2(acc[ti][c][0] + bb.x, acc[ti][c][1] + bb.y);
            float2 o1 = make_float2(acc[ti][c][2] + bb.x, acc[ti][c][3] + bb.y);
            if (tvec) {
                float2 tv0 = *reinterpret_cast<const float2*>(tvp0 + co);
                float2 tv1 = *reinterpret_cast<const float2*>(tvp1 + co);
                o0.x += tv0.x; o0.y += tv0.y;
                o1.x += tv1.x; o1.y += tv1.y;
            }
            if (resid) {
                float2 q0 = *reinterpret_cast<const float2*>(resid + (size_t)r0 * 64 + co);
                float2 q1 = *reinterpret_cast<const float2*>(resid + (size_t)r1 * 64 + co);
                o0.x += q0.x; o0.y += q0.y;
                o1.x += q1.x; o1.y += q1.y;
            }
            *reinterpret_cast<float2*>(out + (size_t)r0 * 64 + co) = o0;
            *reinterpret_cast<float2*>(out + (size_t)r1 * 64 + co) = o1;
        }
    }
}

// ---------------- launch ------------------------------------------------------
extern "C" void kernel_launch(void* const* d_in, const int* in_sizes, int n_in,
                              void* d_out, int out_size) {
    const float* x    = (const float*)d_in[0];
    const float* temb = (const float*)d_in[1];
    const int*   bid  = (const int*)  d_in[2];
    const int*   nei  = (const int*)  d_in[3];
    const float* ga1  = (const float*)d_in[4];
    const float* be1  = (const float*)d_in[5];
    const float* W1   = (const float*)d_in[6];
    const float* b1   = (const float*)d_in[7];
    const float* Wt   = (const float*)d_in[8];
    const float* bt   = (const float*)d_in[9];
    const float* ga2  = (const float*)d_in[10];
    const float* be2  = (const float*)d_in[11];
    const float* W2   = (const float*)d_in[12];
    const float* b2   = (const float*)d_in[13];
    float* out = (float*)d_out;

    __half* h1;
    float *h2, *sum, *ssq, *sum2, *ssq2, *cnt, *tvec;
    uint2 *w1f, *w2f;
    cudaGetSymbolAddress((void**)&h1,   g_h1);
    cudaGetSymbolAddress((void**)&h2,   g_h2);
    cudaGetSymbolAddress((void**)&w1f,  g_w1f);
    cudaGetSymbolAddress((void**)&w2f,  g_w2f);
    cudaGetSymbolAddress((void**)&sum,  g_sum);
    cudaGetSymbolAddress((void**)&ssq,  g_ssq);
    cudaGetSymbolAddress((void**)&sum2, g_sum2);
    cudaGetSymbolAddress((void**)&ssq2, g_ssq2);
    cudaGetSymbolAddress((void**)&cnt,  g_cnt);
    cudaGetSymbolAddress((void**)&tvec, g_tvec);

    cudaFuncSetAttribute(conv_mma_kernel,
                         cudaFuncAttributeMaxDynamicSharedMemorySize, SM_TOTAL);

    const int statsBlocks = N_NODES / 256;       // 512
    const int naBlocks    = (N_NODES * 8) / 256; // 4096
    const int convBlocks  = N_NODES / TN;        // 512

    // prep (weights + zero stats) and time embedding
    prep_kernel<<<217, 256>>>(W1, W2, w1f, w2f, sum, ssq, sum2, ssq2, cnt);
    time_kernel<<<B_DIM, 64>>>(temb, Wt, bt, tvec);

    // GN1 stats -> normact1 (finalize fused) -> h1 fp16
    stats_kernel<<<statsBlocks, 256>>>((const float4*)x, bid, sum, ssq, cnt, 1);
    normact_kernel<<<naBlocks, 256>>>((const float4*)x, bid, sum, ssq, cnt,
                                      ga1, be1, (uint4*)h1);

    // conv1 (fp16 mma.sync, 3-stage per-warp) + t[batch] -> h2
    conv_mma_kernel<<<convBlocks, 256, SM_TOTAL>>>(h1, nei, w1f, b1, tvec, bid, nullptr, h2);

    // GN2 stats (separate buffers) -> normact2 (finalize fused, counts reused)
    stats_kernel<<<statsBlocks, 256>>>((const float4*)h2, bid, sum2, ssq2, cnt, 0);
    normact_kernel<<<naBlocks, 256>>>((const float4*)h2, bid, sum2, ssq2, cnt,
                                      ga2, be2, (uint4*)h1);

    // conv2 (fp16 mma.sync, 3-stage per-warp) + residual -> out
    conv_mma_kernel<<<convBlocks, 256, SM_TOTAL>>>(h1, nei, w2f, b2, nullptr, bid, x, out);
}